// round 15
// baseline (speedup 1.0000x reference)
#include <cuda_runtime.h>
#include <cuda_fp16.h>
#include <math.h>
#include <stdint.h>

#define NN 5000
#define NE 80000
#define HD 128
#define NR 64
#define AS 12
#define MZ 128

#define PI_OVER_CUT 0.6283185307179586f

typedef unsigned long long ull;

__device__ __align__(16) float g_WT[256 * 256];
__device__ __align__(16) float g_ZPt[MZ * HD];
__device__ __align__(16) float g_ZQt[MZ * HD];
__device__ __align__(16) float g_acc[(size_t)NN * HD * AS];  // zero-init; re-zeroed by k5
__device__ __align__(16) __half g_y1h[NN * 256];
__device__ __align__(16) __half g_ws2h[384 * 256];
__device__ __align__(16) float g_nrm[NN * HD * 3];
__device__ __align__(16) __half g_fh[(size_t)NE * 384];
__device__ int g_hist[NN];                           // zero-init; re-zeroed by kg
__device__ int g_cur[NN];
__device__ int g_perm[NE];

__device__ __forceinline__ void red4(float* p, float a, float b, float c, float d) {
    asm volatile("red.global.add.v4.f32 [%0], {%1,%2,%3,%4};"
                 :: "l"(p), "f"(a), "f"(b), "f"(c), "f"(d) : "memory");
}
__device__ __forceinline__ void red2(float* p, float a, float b) {
    asm volatile("red.global.add.v2.f32 [%0], {%1,%2};"
                 :: "l"(p), "f"(a), "f"(b) : "memory");
}
__device__ __forceinline__ ull pk2(float a, float b) {
    ull r;
    asm("mov.b64 %0, {%1,%2};" : "=l"(r) : "f"(a), "f"(b));
    return r;
}
__device__ __forceinline__ void unpk2(ull v, float& a, float& b) {
    asm("mov.b64 {%0,%1}, %2;" : "=f"(a), "=f"(b) : "l"(v));
}
__device__ __forceinline__ ull fma2(ull a, ull b, ull c) {
    ull d;
    asm("fma.rn.f32x2 %0, %1, %2, %3;" : "=l"(d) : "l"(a), "l"(b), "l"(c));
    return d;
}
__device__ __forceinline__ float silu_f(float x) { return x / (1.0f + expf(-x)); }
__device__ __forceinline__ uint32_t smem_u32(const void* p) {
    uint32_t a;
    asm("{ .reg .u64 tmp; cvta.to.shared.u64 tmp, %1; cvt.u32.u64 %0, tmp; }"
        : "=r"(a) : "l"(p));
    return a;
}

// ---------------- 1. kA: khist (blocks 0..156) + W_emb2 transpose (157..188) ----
__global__ __launch_bounds__(512) void kA_histT(const int* __restrict__ ei,
                                                const float* __restrict__ W) {
    const int t = threadIdx.x;
    if (blockIdx.x < 157) {
        int e = blockIdx.x * 512 + t;
        if (e < NE) atomicAdd(&g_hist[ei[e]], 1);
    } else {
        __shared__ float s[32][33];
        int tb = blockIdx.x - 157;
        int c0 = (tb & 7) * 32, h0 = (tb >> 3) * 32;
        int tx = t & 31, ty0 = t >> 5;
        s[ty0][tx]      = W[(h0 + ty0) * 256 + c0 + tx];
        s[ty0 + 16][tx] = W[(h0 + ty0 + 16) * 256 + c0 + tx];
        __syncthreads();
        int k0 = (c0 < 128) ? c0 : c0 - 128;
        int j0 = (c0 < 128) ? h0 : 128 + h0;
        g_WT[(k0 + ty0) * 256 + j0 + tx]      = s[tx][ty0];
        g_WT[(k0 + ty0 + 16) * 256 + j0 + tx] = s[tx][ty0 + 16];
    }
}

// ---------------- 2. kB: scan (blk 0) + k1z tables (1..32) + Ws2->fp16 (33..56) ----
__global__ __launch_bounds__(1024) void kB_multi(const float* __restrict__ emb,
                                                 const float* __restrict__ Ws2) {
    const int t = threadIdx.x;
    if (blockIdx.x == 0) {
        __shared__ int wsum[32];
        __shared__ int carry;
        int lane = t & 31, wid = t >> 5;
        if (t == 0) carry = 0;
        __syncthreads();
        for (int c = 0; c < 5; c++) {
            int idx = c * 1024 + t;
            int v = (idx < NN) ? g_hist[idx] : 0;
            int x = v;
#pragma unroll
            for (int o = 1; o < 32; o <<= 1) {
                int y = __shfl_up_sync(0xffffffffu, x, o);
                if (lane >= o) x += y;
            }
            if (lane == 31) wsum[wid] = x;
            __syncthreads();
            if (wid == 0) {
                int s = wsum[lane];
#pragma unroll
                for (int o = 1; o < 32; o <<= 1) {
                    int y = __shfl_up_sync(0xffffffffu, s, o);
                    if (lane >= o) s += y;
                }
                wsum[lane] = s;
            }
            __syncthreads();
            int pref = carry + (wid ? wsum[wid - 1] : 0) + x - v;
            if (idx < NN) g_cur[idx] = pref;
            __syncthreads();
            if (t == 0) carry += wsum[31];
            __syncthreads();
        }
    } else if (blockIdx.x <= 32) {
        __shared__ float sE[4 * 128];
        int zb = (blockIdx.x - 1) * 4;
        if (t < 4 * 128) sE[t] = emb[(size_t)zb * HD + t];
        __syncthreads();
        int g = t >> 8, j = t & 255;
        int zz = zb + g;
        float a0 = 0.f, a1 = 0.f;
#pragma unroll 8
        for (int k = 0; k < 128; k += 2) {
            a0 += g_WT[k * 256 + j] * sE[g * 128 + k];
            a1 += g_WT[(k + 1) * 256 + j] * sE[g * 128 + k + 1];
        }
        float acc = a0 + a1;
        if (j < 128) g_ZPt[zz * HD + j] = acc;
        else         g_ZQt[zz * HD + j - 128] = acc;
    } else {
        const float2* src = (const float2*)Ws2;
        __half2* dst = (__half2*)g_ws2h;
        int i = (blockIdx.x - 33) * 2048 + t;
        if (t < 1024) {
            dst[i] = __float22half2_rn(src[i]);
            dst[i + 1024] = __float22half2_rn(src[i + 1024]);
        }
    }
}

// ---------------- 3. kg_hmma: edge GEMM (split y-planes, B double-buffered) ----
#define SROW 72
__global__ __launch_bounds__(256) void kg_hmma(
    const float* __restrict__ eattr,
    const float* __restrict__ Wd1, const float* __restrict__ Wd2,
    const float* __restrict__ Wd3, const int* __restrict__ ei) {
    __shared__ __half sA[128 * SROW];
    __shared__ __half sW[128 * SROW];
    const int t = threadIdx.x;
    const int warp = t >> 5, lane = t & 31;
    const int e0 = blockIdx.x * 128;
    const int y = blockIdx.y;
    const float* W = (y == 0) ? Wd1 : ((y == 1) ? Wd2 : Wd3);

    if (y == 1) {
        int e = blockIdx.x * 256 + t;
        if (e < NE) {
            int s = ei[e];
            int p = atomicAdd(&g_cur[s], 1);
            g_perm[p] = e;
        }
    } else if (y == 2) {
        int i = blockIdx.x * 256 + t;
        if (i < NN) g_hist[i] = 0;
    }

    {
        const float2* srcA = (const float2*)(eattr + (size_t)e0 * NR);
        const float2* srcW = (const float2*)W;
#pragma unroll
        for (int r = 0; r < 16; r++) {
            int i = t + 256 * r;
            int row = i >> 5, c2 = i & 31;
            *(__half2*)&sA[row * SROW + c2 * 2] = __float22half2_rn(srcA[i]);
            *(__half2*)&sW[row * SROW + c2 * 2] = __float22half2_rn(srcW[i]);
        }
    }
    __syncthreads();

    const uint32_t sAb = smem_u32(sA);
    const uint32_t sWb = smem_u32(sW);

    uint32_t af[4][4];
#pragma unroll
    for (int ks = 0; ks < 4; ks++) {
        uint32_t addr = sAb +
            2 * ((uint32_t)(warp * 16 + (lane & 15)) * SROW + ks * 16 + (lane >> 4) * 8);
        asm volatile("ldmatrix.sync.aligned.m8n8.x4.shared.b16 {%0,%1,%2,%3}, [%4];"
                     : "=r"(af[ks][0]), "=r"(af[ks][1]), "=r"(af[ks][2]), "=r"(af[ks][3])
                     : "r"(addr));
    }

    float d[16][4];
#pragma unroll
    for (int n = 0; n < 16; n++)
#pragma unroll
        for (int c = 0; c < 4; c++) d[n][c] = 0.f;

#define LDB(nn, kks, buf)                                                        \
    do {                                                                         \
        uint32_t addr_ = sWb + 2 * ((uint32_t)((nn) * 8 + (lane & 7)) * SROW +   \
                                    (kks) * 16 + ((lane >> 3) & 1) * 8);         \
        asm volatile("ldmatrix.sync.aligned.m8n8.x2.shared.b16 {%0,%1}, [%2];"   \
                     : "=r"(bb[buf][0]), "=r"(bb[buf][1]) : "r"(addr_));         \
    } while (0)

    uint32_t bb[2][2];
    LDB(0, 0, 0);
#pragma unroll
    for (int idx = 0; idx < 64; idx++) {
        int n = idx >> 2, ks = idx & 3;
        int buf = idx & 1;
        if (idx < 63) {
            int n2 = (idx + 1) >> 2, ks2 = (idx + 1) & 3;
            LDB(n2, ks2, buf ^ 1);
        }
        asm volatile(
            "mma.sync.aligned.m16n8k16.row.col.f32.f16.f16.f32 "
            "{%0,%1,%2,%3}, {%4,%5,%6,%7}, {%8,%9}, {%0,%1,%2,%3};"
            : "+f"(d[n][0]), "+f"(d[n][1]), "+f"(d[n][2]), "+f"(d[n][3])
            : "r"(af[ks][0]), "r"(af[ks][1]), "r"(af[ks][2]), "r"(af[ks][3]),
              "r"(bb[buf][0]), "r"(bb[buf][1]));
    }
#undef LDB

    {
        int r0 = lane >> 2, cb = (lane & 3) * 2;
        size_t base0 = (size_t)(e0 + warp * 16 + r0) * 384 + y * 128;
        size_t base1 = (size_t)(e0 + warp * 16 + r0 + 8) * 384 + y * 128;
#pragma unroll
        for (int n = 0; n < 16; n++) {
            *(__half2*)&g_fh[base0 + n * 8 + cb] = __floats2half2_rn(d[n][0], d[n][1]);
            *(__half2*)&g_fh[base1 + n * 8 + cb] = __floats2half2_rn(d[n][2], d[n][3]);
        }
    }
}

// ---------------- 4. ke: epilogue (4-edge prefetch) — PROFILED ----------------
__global__ __launch_bounds__(512) void ke_epi(
    const int* __restrict__ ei, const float* __restrict__ ew,
    const float* __restrict__ evec, const int* __restrict__ z,
    const float* __restrict__ b_emb2,
    const float* __restrict__ bd1, const float* __restrict__ bd2,
    const float* __restrict__ bd3) {
    __shared__ float sCut[64], sVx[64], sVy[64], sVz[64];
    __shared__ int sSrc[64], sZs[64], sZd[64], sPe[64];
    const int tid = threadIdx.x;
    const int e0 = blockIdx.x * 64;
    if (tid < 64) {
        int pe = g_perm[e0 + tid];
        sPe[tid] = pe;
        int s = ei[pe], d = ei[NE + pe];
        sSrc[tid] = s;
        sZs[tid] = z[s];
        sZd[tid] = z[d];
        float w = ew[pe];
        sCut[tid] = (w < 5.0f) ? 0.5f * (cosf(w * PI_OVER_CUT) + 1.0f) : 0.0f;
        sVx[tid] = evec[3 * pe + 0];
        sVy[tid] = evec[3 * pe + 1];
        sVz[tid] = evec[3 * pe + 2];
    }
    __syncthreads();

    const int h = tid & 127;
    const int grp = tid >> 7;
    const float bemb = b_emb2[h];
    const float b1 = bd1[h], b2 = bd2[h], b3 = bd3[h];

    float racc[10];
#pragma unroll
    for (int c = 0; c < 10; c++) racc[c] = 0.f;
    int cur = sSrc[grp * 16];

#define FLUSH()                                                  \
    do {                                                         \
        float* p_ = &g_acc[((size_t)cur * HD + h) * AS];         \
        red4(p_, racc[0], racc[1], racc[2], racc[3]);            \
        red4(p_ + 4, racc[4], racc[5], racc[6], racc[7]);        \
        red2(p_ + 8, racc[8], racc[9]);                          \
    } while (0)

    for (int c4 = 0; c4 < 4; c4++) {
        int eb = grp * 16 + c4 * 4;
        float f1v[4], f2v[4], f3v[4], Cv[4];
#pragma unroll
        for (int i = 0; i < 4; i++) {
            int e = eb + i;
            const __half* fp = &g_fh[(size_t)sPe[e] * 384 + h];
            f1v[i] = __half2float(fp[0]);
            f2v[i] = __half2float(fp[128]);
            f3v[i] = __half2float(fp[256]);
            Cv[i] = sCut[e] * (g_ZPt[sZs[e] * HD + h] + g_ZQt[sZd[e] * HD + h] + bemb);
        }
#pragma unroll
        for (int i = 0; i < 4; i++) {
            int e = eb + i;
            int s = sSrc[e];
            float C = Cv[i];
            float f1 = (f1v[i] + b1) * C;
            float f2 = (f2v[i] + b2) * C;
            float f3 = (f3v[i] + b3) * C;
            if (s != cur) {
                FLUSH();
#pragma unroll
                for (int c = 0; c < 10; c++) racc[c] = 0.f;
                cur = s;
            }
            float vx = sVx[e], vy = sVy[e], vz = sVz[e];
            racc[0] += f1;
            racc[1] += f2 * vx; racc[2] += f2 * vy; racc[3] += f2 * vz;
            float f3x = f3 * vx, f3y = f3 * vy, f3z = f3 * vz;
            racc[4] += f3x * vx; racc[5] += f3x * vy; racc[6] += f3x * vz;
            racc[7] += f3y * vy; racc[8] += f3y * vz; racc[9] += f3z * vz;
        }
    }
    FLUSH();
#undef FLUSH
}

// ---------------- 5. k4a: fused tn+LN + y1h = silu(Ws1 @ ln + bs1) [20 nodes/blk] ----
__global__ __launch_bounds__(256, 3) void k4a_gemm(
    const float* __restrict__ Ws1, const float* __restrict__ bs1,
    const float* __restrict__ ln_g, const float* __restrict__ ln_b) {
    __shared__ float sXT[HD * 20];
    __shared__ float sW[16 * 257];
    __shared__ float sT[20 * HD];
    __shared__ float sMu[20], sRs[20];
    const int t = threadIdx.x;
    const int nb = blockIdx.x * 20;

    // tn per (node, h)
    for (int i = t; i < 20 * HD; i += 256) {
        int nl = i >> 7, hh = i & 127;
        const float* a = &g_acc[((size_t)(nb + nl) * HD + hh) * AS];
        float4 p0 = *(const float4*)a;
        float4 p1 = *(const float4*)(a + 4);
        float2 p2 = *(const float2*)(a + 8);
        float s1 = p0.x, wx = p0.y, wy = p0.z, wz = p0.w;
        float mxx = p1.x, mxy = p1.y, mxz = p1.z, myy = p1.w, myz = p2.x, mzz = p2.y;
        float tr3 = (mxx + myy + mzz) * (1.0f / 3.0f);
        float dxx = s1 + mxx - tr3, dyy = s1 + myy - tr3, dzz = s1 + mzz - tr3;
        float t01 = mxy - wz, t10 = mxy + wz, t02 = mxz + wy;
        float t20 = mxz - wy, t12 = myz - wx, t21 = myz + wx;
        sT[nl * HD + hh] = dxx * dxx + dyy * dyy + dzz * dzz + t01 * t01 + t10 * t10 +
                           t02 * t02 + t20 * t20 + t12 * t12 + t21 * t21;
    }
    __syncthreads();
    // per-node mean / rstd
    {
        int warp = t >> 5, lane = t & 31;
        for (int node = warp; node < 20; node += 8) {
            float s = 0.f, ss = 0.f;
#pragma unroll
            for (int j = lane; j < HD; j += 32) {
                float v = sT[node * HD + j];
                s += v; ss += v * v;
            }
#pragma unroll
            for (int o = 16; o; o >>= 1) {
                s  += __shfl_xor_sync(0xffffffffu, s, o);
                ss += __shfl_xor_sync(0xffffffffu, ss, o);
            }
            if (lane == 0) {
                float mu = s * (1.0f / HD);
                sMu[node] = mu;
                sRs[node] = rsqrtf(ss * (1.0f / HD) - mu * mu + 1e-5f);
            }
        }
    }
    __syncthreads();
    // LN -> transposed staging
    for (int i = t; i < 20 * HD; i += 256) {
        int nl = i >> 7, hh = i & 127;
        sXT[hh * 20 + nl] =
            (sT[nl * HD + hh] - sMu[nl]) * sRs[nl] * ln_g[hh] + ln_b[hh];
    }

    ull acc[10];
#pragma unroll
    for (int c = 0; c < 10; c++) acc[c] = 0ull;

    for (int h0 = 0; h0 < HD; h0 += 16) {
        __syncthreads();
#pragma unroll
        for (int r = 0; r < 16; r++) {
            int i = t + 256 * r;
            int j = i >> 4, hh = i & 15;
            sW[hh * 257 + j] = Ws1[j * HD + h0 + hh];
        }
        __syncthreads();
#pragma unroll 4
        for (int hh = 0; hh < 16; hh++) {
            float w = sW[hh * 257 + t];
            ull wp = pk2(w, w);
            const ulonglong2* xp = (const ulonglong2*)&sXT[(h0 + hh) * 20];
            ulonglong2 x0 = xp[0], x1 = xp[1];
            ulonglong2 x2 = xp[2], x3 = xp[3];
            ulonglong2 x4 = xp[4];
            acc[0] = fma2(wp, x0.x, acc[0]);
            acc[1] = fma2(wp, x0.y, acc[1]);
            acc[2] = fma2(wp, x1.x, acc[2]);
            acc[3] = fma2(wp, x1.y, acc[3]);
            acc[4] = fma2(wp, x2.x, acc[4]);
            acc[5] = fma2(wp, x2.y, acc[5]);
            acc[6] = fma2(wp, x3.x, acc[6]);
            acc[7] = fma2(wp, x3.y, acc[7]);
            acc[8] = fma2(wp, x4.x, acc[8]);
            acc[9] = fma2(wp, x4.y, acc[9]);
        }
    }
    float bb = bs1[t];
#pragma unroll
    for (int c = 0; c < 10; c++) {
        float a0, a1;
        unpk2(acc[c], a0, a1);
        g_y1h[(size_t)(nb + 2 * c) * 256 + t]     = __float2half(silu_f(a0 + bb));
        g_y1h[(size_t)(nb + 2 * c + 1) * 256 + t] = __float2half(silu_f(a1 + bb));
    }
}

// ---------------- 6. k4b_hmma: nrm = silu(Ws2 @ y1 + bs2) via HMMA ----------------
__global__ __launch_bounds__(256) void k4b_hmma(const float* __restrict__ bs2) {
    __shared__ __half sA[128 * SROW];
    __shared__ __half sB[128 * SROW];
    const int t = threadIdx.x;
    const int warp = t >> 5, lane = t & 31;
    const int nt0 = blockIdx.x * 128;
    const int jt0 = blockIdx.y * 128;

    const uint32_t sAb = smem_u32(sA);
    const uint32_t sBb = smem_u32(sB);

    float d[16][4];
#pragma unroll
    for (int n = 0; n < 16; n++)
#pragma unroll
        for (int c = 0; c < 4; c++) d[n][c] = 0.f;

    for (int kc = 0; kc < 4; kc++) {
        __syncthreads();
#pragma unroll
        for (int r = 0; r < 4; r++) {
            int i = t + 256 * r;
            int row = i >> 3, c8 = (i & 7) * 8;
            *(uint4*)&sA[row * SROW + c8] =
                *(const uint4*)&g_ws2h[(size_t)(jt0 + row) * 256 + kc * 64 + c8];
            int node = nt0 + row;
            uint4 v = make_uint4(0u, 0u, 0u, 0u);
            if (node < NN)
                v = *(const uint4*)&g_y1h[(size_t)node * 256 + kc * 64 + c8];
            *(uint4*)&sB[row * SROW + c8] = v;
        }
        __syncthreads();

#pragma unroll
        for (int ks = 0; ks < 4; ks++) {
            uint32_t af[4];
            uint32_t addr = sAb +
                2 * ((uint32_t)(warp * 16 + (lane & 15)) * SROW + ks * 16 + (lane >> 4) * 8);
            asm volatile("ldmatrix.sync.aligned.m8n8.x4.shared.b16 {%0,%1,%2,%3}, [%4];"
                         : "=r"(af[0]), "=r"(af[1]), "=r"(af[2]), "=r"(af[3]) : "r"(addr));
#pragma unroll
            for (int n = 0; n < 16; n++) {
                uint32_t b0, b1;
                uint32_t baddr = sBb +
                    2 * ((uint32_t)(n * 8 + (lane & 7)) * SROW + ks * 16 + ((lane >> 3) & 1) * 8);
                asm volatile("ldmatrix.sync.aligned.m8n8.x2.shared.b16 {%0,%1}, [%2];"
                             : "=r"(b0), "=r"(b1) : "r"(baddr));
                asm volatile(
                    "mma.sync.aligned.m16n8k16.row.col.f32.f16.f16.f32 "
                    "{%0,%1,%2,%3}, {%4,%5,%6,%7}, {%8,%9}, {%0,%1,%2,%3};"
                    : "+f"(d[n][0]), "+f"(d[n][1]), "+f"(d[n][2]), "+f"(d[n][3])
                    : "r"(af[0]), "r"(af[1]), "r"(af[2]), "r"(af[3]), "r"(b0), "r"(b1));
            }
        }
    }

    {
        int r0 = lane >> 2, cb = (lane & 3) * 2;
        int j0 = jt0 + warp * 16 + r0;
        float bb0 = bs2[j0], bb1 = bs2[j0 + 8];
#pragma unroll
        for (int n = 0; n < 16; n++) {
            int node0 = nt0 + n * 8 + cb;
            if (node0 < NN) {
                g_nrm[(size_t)node0 * 384 + j0]     = silu_f(d[n][0] + bb0);
                g_nrm[(size_t)node0 * 384 + j0 + 8] = silu_f(d[n][2] + bb1);
            }
            if (node0 + 1 < NN) {
                g_nrm[(size_t)(node0 + 1) * 384 + j0]     = silu_f(d[n][1] + bb0);
                g_nrm[(size_t)(node0 + 1) * 384 + j0 + 8] = silu_f(d[n][3] + bb1);
            }
        }
    }
}

// ---------------- 7. k5: Wt transforms + output (12 nodes/blk, 2g x 3nl tile) ----
#define K5NB 12
__global__ __launch_bounds__(256, 2) void k5_out(
    const float* __restrict__ Wt1, const float* __restrict__ Wt2,
    const float* __restrict__ Wt3, float* __restrict__ out) {
    extern __shared__ float sm[];
    float* sAcc = sm;                   // [12][128][12]
    float* sWt  = sm + K5NB * HD * AS;  // [8][390]
    int t  = threadIdx.x;
    int nb = blockIdx.x * K5NB;
    {
        float4* gsrc = (float4*)&g_acc[(size_t)nb * HD * AS];
        float4* dst = (float4*)sAcc;
        for (int i = t; i < K5NB * HD * 3; i += 256) {
            int node = nb + i / (HD * 3);
            if (node < NN) dst[i] = gsrc[i];
        }
        __syncthreads();
        float4 zz = make_float4(0.f, 0.f, 0.f, 0.f);
        for (int i = t; i < K5NB * HD * 3; i += 256) {
            int node = nb + i / (HD * 3);
            if (node < NN) gsrc[i] = zz;
        }
    }

    const int g0 = (t & 63) * 2;
    const int n0 = (t >> 6) * 3;

    ull acc[2][3][5];
#pragma unroll
    for (int gi = 0; gi < 2; gi++)
#pragma unroll
        for (int ni = 0; ni < 3; ni++)
#pragma unroll
            for (int c = 0; c < 5; c++) acc[gi][ni][c] = 0ull;

    for (int h0 = 0; h0 < HD; h0 += 8) {
        __syncthreads();
#pragma unroll
        for (int r = 0; r < 12; r++) {
            int i = t + 256 * r;
            int m = i >> 10;
            int rr = i & 1023;
            int gg = rr >> 3, hh = rr & 7;
            const float* W = (m == 0) ? Wt1 : ((m == 1) ? Wt2 : Wt3);
            sWt[hh * 390 + m * 128 + gg] = W[gg * HD + h0 + hh];
        }
        __syncthreads();
#pragma unroll
        for (int hh = 0; hh < 8; hh++) {
            const float* wrow = &sWt[hh * 390];
            float2 w1 = *(const float2*)&wrow[g0];
            float2 w2 = *(const float2*)&wrow[128 + g0];
            float2 w3 = *(const float2*)&wrow[256 + g0];
            ull pw12a = pk2(w1.x, w2.x), pw22a = pk2(w2.x, w2.x), pw33a = pk2(w3.x, w3.x);
            ull pw12b = pk2(w1.y, w2.y), pw22b = pk2(w2.y, w2.y), pw33b = pk2(w3.y, w3.y);
#pragma unroll
            for (int ni = 0; ni < 3; ni++) {
                const ull* ap = (const ull*)&sAcc[((n0 + ni) * HD + h0 + hh) * AS];
                ulonglong2 q0 = *(const ulonglong2*)ap;
                ulonglong2 q1 = *(const ulonglong2*)(ap + 2);
                ull q2 = ap[4];
                acc[0][ni][0] = fma2(pw12a, q0.x, acc[0][ni][0]);
                acc[0][ni][1] = fma2(pw22a, q0.y, acc[0][ni][1]);
                acc[0][ni][2] = fma2(pw33a, q1.x, acc[0][ni][2]);
                acc[0][ni][3] = fma2(pw33a, q1.y, acc[0][ni][3]);
                acc[0][ni][4] = fma2(pw33a, q2,   acc[0][ni][4]);
                acc[1][ni][0] = fma2(pw12b, q0.x, acc[1][ni][0]);
                acc[1][ni][1] = fma2(pw22b, q0.y, acc[1][ni][1]);
                acc[1][ni][2] = fma2(pw33b, q1.x, acc[1][ni][2]);
                acc[1][ni][3] = fma2(pw33b, q1.y, acc[1][ni][3]);
                acc[1][ni][4] = fma2(pw33b, q2,   acc[1][ni][4]);
            }
        }
    }

#pragma unroll
    for (int gi = 0; gi < 2; gi++)
#pragma unroll
    for (int ni = 0; ni < 3; ni++) {
        int n = nb + n0 + ni;
        if (n >= NN) continue;
        int g = g0 + gi;
        float nr0 = g_nrm[(size_t)n * 384 + g * 3 + 0];
        float nr1 = g_nrm[(size_t)n * 384 + g * 3 + 1];
        float nr2 = g_nrm[(size_t)n * 384 + g * 3 + 2];
        float s1, wx, wy, wz, mxx, mxy, mxz, myy, myz, mzz;
        unpk2(acc[gi][ni][0], s1, wx);
        unpk2(acc[gi][ni][1], wy, wz);
        unpk2(acc[gi][ni][2], mxx, mxy);
        unpk2(acc[gi][ni][3], mxz, myy);
        unpk2(acc[gi][ni][4], myz, mzz);
        float tr3 = (mxx + myy + mzz) * (1.0f / 3.0f);
        float dI = nr0 * s1;
        float* o = out + ((size_t)n * HD + g) * 9;
        o[0] = dI + nr2 * (mxx - tr3);
        o[1] = -nr1 * wz + nr2 * mxy;
        o[2] =  nr1 * wy + nr2 * mxz;
        o[3] =  nr1 * wz + nr2 * mxy;
        o[4] = dI + nr2 * (myy - tr3);
        o[5] = -nr1 * wx + nr2 * myz;
        o[6] = -nr1 * wy + nr2 * mxz;
        o[7] =  nr1 * wx + nr2 * myz;
        o[8] = dI + nr2 * (mzz - tr3);
    }
}

#define K5_SMEM ((K5NB * HD * AS + 8 * 390) * 4)

extern "C" void kernel_launch(void* const* d_in, const int* in_sizes, int n_in,
                              void* d_out, int out_size) {
    (void)in_sizes; (void)n_in; (void)out_size;
    const int*   z      = (const int*)d_in[0];
    const int*   ei     = (const int*)d_in[1];
    const float* ew     = (const float*)d_in[2];
    const float* evec   = (const float*)d_in[3];
    const float* eattr  = (const float*)d_in[4];
    const float* emb    = (const float*)d_in[5];
    const float* W_emb2 = (const float*)d_in[6];
    const float* b_emb2 = (const float*)d_in[7];
    const float* Wd1 = (const float*)d_in[8],  *bd1 = (const float*)d_in[9];
    const float* Wd2 = (const float*)d_in[10], *bd2 = (const float*)d_in[11];
    const float* Wd3 = (const float*)d_in[12], *bd3 = (const float*)d_in[13];
    const float* Wt1 = (const float*)d_in[14], *Wt2 = (const float*)d_in[15];
    const float* Wt3 = (const float*)d_in[16];
    const float* Ws1 = (const float*)d_in[17], *bs1 = (const float*)d_in[18];
    const float* Ws2 = (const float*)d_in[19], *bs2 = (const float*)d_in[20];
    const float* ln_g = (const float*)d_in[21], *ln_b = (const float*)d_in[22];
    float* out = (float*)d_out;

    cudaFuncSetAttribute(k5_out, cudaFuncAttributeMaxDynamicSharedMemorySize, K5_SMEM);

    kA_histT<<<189, 512>>>(ei, W_emb2);                                 // 1
    kB_multi<<<57, 1024>>>(emb, Ws2);                                   // 2
    kg_hmma<<<dim3(NE / 128, 3), 256>>>(eattr, Wd1, Wd2, Wd3, ei);      // 3
    ke_epi<<<NE / 64, 512>>>(ei, ew, evec, z, b_emb2, bd1, bd2, bd3);   // 4 <- PROFILED
    k4a_gemm<<<NN / 20, 256>>>(Ws1, bs1, ln_g, ln_b);                   // 5 (fused LN)
    k4b_hmma<<<dim3(40, 3), 256>>>(bs2);                                // 6
    k5_out<<<(NN + K5NB - 1) / K5NB, 256, K5_SMEM>>>(Wt1, Wt2, Wt3, out); // 7
}

// round 16
// speedup vs baseline: 1.0081x; 1.0081x over previous
#include <cuda_runtime.h>
#include <cuda_fp16.h>
#include <math.h>
#include <stdint.h>

#define NN 5000
#define NE 80000
#define HD 128
#define NR 64
#define AS 12
#define MZ 128

#define PI_OVER_CUT 0.6283185307179586f

typedef unsigned long long ull;

__device__ __align__(16) float g_WT[256 * 256];
__device__ __align__(16) float g_ZPt[MZ * HD];
__device__ __align__(16) float g_ZQt[MZ * HD];
__device__ __align__(16) float g_acc[(size_t)NN * HD * AS];  // zero-init; re-zeroed by k5
__device__ __align__(16) __half g_y1h[NN * 256];
__device__ __align__(16) __half g_ws2h[384 * 256];
__device__ __align__(16) float g_nrm[NN * HD * 3];
__device__ __align__(16) __half g_fh[(size_t)NE * 384];
__device__ int g_hist[NN];                           // zero-init; re-zeroed by kg
__device__ int g_cur[NN];
__device__ int g_perm[NE];

__device__ __forceinline__ void red4(float* p, float a, float b, float c, float d) {
    asm volatile("red.global.add.v4.f32 [%0], {%1,%2,%3,%4};"
                 :: "l"(p), "f"(a), "f"(b), "f"(c), "f"(d) : "memory");
}
__device__ __forceinline__ void red2(float* p, float a, float b) {
    asm volatile("red.global.add.v2.f32 [%0], {%1,%2};"
                 :: "l"(p), "f"(a), "f"(b) : "memory");
}
__device__ __forceinline__ ull pk2(float a, float b) {
    ull r;
    asm("mov.b64 %0, {%1,%2};" : "=l"(r) : "f"(a), "f"(b));
    return r;
}
__device__ __forceinline__ void unpk2(ull v, float& a, float& b) {
    asm("mov.b64 {%0,%1}, %2;" : "=f"(a), "=f"(b) : "l"(v));
}
__device__ __forceinline__ ull fma2(ull a, ull b, ull c) {
    ull d;
    asm("fma.rn.f32x2 %0, %1, %2, %3;" : "=l"(d) : "l"(a), "l"(b), "l"(c));
    return d;
}
__device__ __forceinline__ float silu_f(float x) { return x / (1.0f + expf(-x)); }
__device__ __forceinline__ uint32_t smem_u32(const void* p) {
    uint32_t a;
    asm("{ .reg .u64 tmp; cvta.to.shared.u64 tmp, %1; cvt.u32.u64 %0, tmp; }"
        : "=r"(a) : "l"(p));
    return a;
}

// ---------------- 1. kA: khist (blocks 0..156) + W_emb2 transpose (157..188) ----
__global__ __launch_bounds__(512) void kA_histT(const int* __restrict__ ei,
                                                const float* __restrict__ W) {
    const int t = threadIdx.x;
    if (blockIdx.x < 157) {
        int e = blockIdx.x * 512 + t;
        if (e < NE) atomicAdd(&g_hist[ei[e]], 1);
    } else {
        __shared__ float s[32][33];
        int tb = blockIdx.x - 157;
        int c0 = (tb & 7) * 32, h0 = (tb >> 3) * 32;
        int tx = t & 31, ty0 = t >> 5;
        s[ty0][tx]      = W[(h0 + ty0) * 256 + c0 + tx];
        s[ty0 + 16][tx] = W[(h0 + ty0 + 16) * 256 + c0 + tx];
        __syncthreads();
        int k0 = (c0 < 128) ? c0 : c0 - 128;
        int j0 = (c0 < 128) ? h0 : 128 + h0;
        g_WT[(k0 + ty0) * 256 + j0 + tx]      = s[tx][ty0];
        g_WT[(k0 + ty0 + 16) * 256 + j0 + tx] = s[tx][ty0 + 16];
    }
}

// ---------------- 2. kB: scan (blk 0) + k1z tables (1..32) + Ws2->fp16 (33..56) ----
__global__ __launch_bounds__(1024) void kB_multi(const float* __restrict__ emb,
                                                 const float* __restrict__ Ws2) {
    const int t = threadIdx.x;
    if (blockIdx.x == 0) {
        __shared__ int wsum[32];
        __shared__ int carry;
        int lane = t & 31, wid = t >> 5;
        if (t == 0) carry = 0;
        __syncthreads();
        for (int c = 0; c < 5; c++) {
            int idx = c * 1024 + t;
            int v = (idx < NN) ? g_hist[idx] : 0;
            int x = v;
#pragma unroll
            for (int o = 1; o < 32; o <<= 1) {
                int y = __shfl_up_sync(0xffffffffu, x, o);
                if (lane >= o) x += y;
            }
            if (lane == 31) wsum[wid] = x;
            __syncthreads();
            if (wid == 0) {
                int s = wsum[lane];
#pragma unroll
                for (int o = 1; o < 32; o <<= 1) {
                    int y = __shfl_up_sync(0xffffffffu, s, o);
                    if (lane >= o) s += y;
                }
                wsum[lane] = s;
            }
            __syncthreads();
            int pref = carry + (wid ? wsum[wid - 1] : 0) + x - v;
            if (idx < NN) g_cur[idx] = pref;
            __syncthreads();
            if (t == 0) carry += wsum[31];
            __syncthreads();
        }
    } else if (blockIdx.x <= 32) {
        __shared__ float sE[4 * 128];
        int zb = (blockIdx.x - 1) * 4;
        if (t < 4 * 128) sE[t] = emb[(size_t)zb * HD + t];
        __syncthreads();
        int g = t >> 8, j = t & 255;
        int zz = zb + g;
        float a0 = 0.f, a1 = 0.f;
#pragma unroll 8
        for (int k = 0; k < 128; k += 2) {
            a0 += g_WT[k * 256 + j] * sE[g * 128 + k];
            a1 += g_WT[(k + 1) * 256 + j] * sE[g * 128 + k + 1];
        }
        float acc = a0 + a1;
        if (j < 128) g_ZPt[zz * HD + j] = acc;
        else         g_ZQt[zz * HD + j - 128] = acc;
    } else {
        const float2* src = (const float2*)Ws2;
        __half2* dst = (__half2*)g_ws2h;
        int i = (blockIdx.x - 33) * 2048 + t;
        if (t < 1024) {
            dst[i] = __float22half2_rn(src[i]);
            dst[i + 1024] = __float22half2_rn(src[i + 1024]);
        }
    }
}

// ---------------- 3. kg_hmma: edge GEMM (split y-planes, R12/R14 inner loop) ----
#define SROW 72
__global__ __launch_bounds__(256) void kg_hmma(
    const float* __restrict__ eattr,
    const float* __restrict__ Wd1, const float* __restrict__ Wd2,
    const float* __restrict__ Wd3, const int* __restrict__ ei) {
    __shared__ __half sA[128 * SROW];
    __shared__ __half sW[128 * SROW];
    const int t = threadIdx.x;
    const int warp = t >> 5, lane = t & 31;
    const int e0 = blockIdx.x * 128;
    const int y = blockIdx.y;
    const float* W = (y == 0) ? Wd1 : ((y == 1) ? Wd2 : Wd3);

    if (y == 1) {
        int e = blockIdx.x * 256 + t;
        if (e < NE) {
            int s = ei[e];
            int p = atomicAdd(&g_cur[s], 1);
            g_perm[p] = e;
        }
    } else if (y == 2) {
        int i = blockIdx.x * 256 + t;
        if (i < NN) g_hist[i] = 0;
    }

    {
        const float2* srcA = (const float2*)(eattr + (size_t)e0 * NR);
        const float2* srcW = (const float2*)W;
#pragma unroll
        for (int r = 0; r < 16; r++) {
            int i = t + 256 * r;
            int row = i >> 5, c2 = i & 31;
            *(__half2*)&sA[row * SROW + c2 * 2] = __float22half2_rn(srcA[i]);
            *(__half2*)&sW[row * SROW + c2 * 2] = __float22half2_rn(srcW[i]);
        }
    }
    __syncthreads();

    const uint32_t sAb = smem_u32(sA);
    const uint32_t sWb = smem_u32(sW);

    uint32_t af[4][4];
#pragma unroll
    for (int ks = 0; ks < 4; ks++) {
        uint32_t addr = sAb +
            2 * ((uint32_t)(warp * 16 + (lane & 15)) * SROW + ks * 16 + (lane >> 4) * 8);
        asm volatile("ldmatrix.sync.aligned.m8n8.x4.shared.b16 {%0,%1,%2,%3}, [%4];"
                     : "=r"(af[ks][0]), "=r"(af[ks][1]), "=r"(af[ks][2]), "=r"(af[ks][3])
                     : "r"(addr));
    }

    float d[16][4];
#pragma unroll
    for (int n = 0; n < 16; n++)
#pragma unroll
        for (int c = 0; c < 4; c++) d[n][c] = 0.f;

#pragma unroll
    for (int n = 0; n < 16; n++) {
#pragma unroll
        for (int ks = 0; ks < 4; ks++) {
            uint32_t b0, b1;
            uint32_t addr = sWb +
                2 * ((uint32_t)(n * 8 + (lane & 7)) * SROW + ks * 16 + ((lane >> 3) & 1) * 8);
            asm volatile("ldmatrix.sync.aligned.m8n8.x2.shared.b16 {%0,%1}, [%2];"
                         : "=r"(b0), "=r"(b1) : "r"(addr));
            asm volatile(
                "mma.sync.aligned.m16n8k16.row.col.f32.f16.f16.f32 "
                "{%0,%1,%2,%3}, {%4,%5,%6,%7}, {%8,%9}, {%0,%1,%2,%3};"
                : "+f"(d[n][0]), "+f"(d[n][1]), "+f"(d[n][2]), "+f"(d[n][3])
                : "r"(af[ks][0]), "r"(af[ks][1]), "r"(af[ks][2]), "r"(af[ks][3]),
                  "r"(b0), "r"(b1));
        }
    }

    {
        int r0 = lane >> 2, cb = (lane & 3) * 2;
        size_t base0 = (size_t)(e0 + warp * 16 + r0) * 384 + y * 128;
        size_t base1 = (size_t)(e0 + warp * 16 + r0 + 8) * 384 + y * 128;
#pragma unroll
        for (int n = 0; n < 16; n++) {
            *(__half2*)&g_fh[base0 + n * 8 + cb] = __floats2half2_rn(d[n][0], d[n][1]);
            *(__half2*)&g_fh[base1 + n * 8 + cb] = __floats2half2_rn(d[n][2], d[n][3]);
        }
    }
}

// ---------------- 4. ke: epilogue (4-edge prefetch) — PROFILED ----------------
__global__ __launch_bounds__(512) void ke_epi(
    const int* __restrict__ ei, const float* __restrict__ ew,
    const float* __restrict__ evec, const int* __restrict__ z,
    const float* __restrict__ b_emb2,
    const float* __restrict__ bd1, const float* __restrict__ bd2,
    const float* __restrict__ bd3) {
    __shared__ float sCut[64], sVx[64], sVy[64], sVz[64];
    __shared__ int sSrc[64], sZs[64], sZd[64], sPe[64];
    const int tid = threadIdx.x;
    const int e0 = blockIdx.x * 64;
    if (tid < 64) {
        int pe = g_perm[e0 + tid];
        sPe[tid] = pe;
        int s = ei[pe], d = ei[NE + pe];
        sSrc[tid] = s;
        sZs[tid] = z[s];
        sZd[tid] = z[d];
        float w = ew[pe];
        sCut[tid] = (w < 5.0f) ? 0.5f * (cosf(w * PI_OVER_CUT) + 1.0f) : 0.0f;
        sVx[tid] = evec[3 * pe + 0];
        sVy[tid] = evec[3 * pe + 1];
        sVz[tid] = evec[3 * pe + 2];
    }
    __syncthreads();

    const int h = tid & 127;
    const int grp = tid >> 7;
    const float bemb = b_emb2[h];
    const float b1 = bd1[h], b2 = bd2[h], b3 = bd3[h];

    float racc[10];
#pragma unroll
    for (int c = 0; c < 10; c++) racc[c] = 0.f;
    int cur = sSrc[grp * 16];

#define FLUSH()                                                  \
    do {                                                         \
        float* p_ = &g_acc[((size_t)cur * HD + h) * AS];         \
        red4(p_, racc[0], racc[1], racc[2], racc[3]);            \
        red4(p_ + 4, racc[4], racc[5], racc[6], racc[7]);        \
        red2(p_ + 8, racc[8], racc[9]);                          \
    } while (0)

    for (int c4 = 0; c4 < 4; c4++) {
        int eb = grp * 16 + c4 * 4;
        float f1v[4], f2v[4], f3v[4], Cv[4];
#pragma unroll
        for (int i = 0; i < 4; i++) {
            int e = eb + i;
            const __half* fp = &g_fh[(size_t)sPe[e] * 384 + h];
            f1v[i] = __half2float(fp[0]);
            f2v[i] = __half2float(fp[128]);
            f3v[i] = __half2float(fp[256]);
            Cv[i] = sCut[e] * (g_ZPt[sZs[e] * HD + h] + g_ZQt[sZd[e] * HD + h] + bemb);
        }
#pragma unroll
        for (int i = 0; i < 4; i++) {
            int e = eb + i;
            int s = sSrc[e];
            float C = Cv[i];
            float f1 = (f1v[i] + b1) * C;
            float f2 = (f2v[i] + b2) * C;
            float f3 = (f3v[i] + b3) * C;
            if (s != cur) {
                FLUSH();
#pragma unroll
                for (int c = 0; c < 10; c++) racc[c] = 0.f;
                cur = s;
            }
            float vx = sVx[e], vy = sVy[e], vz = sVz[e];
            racc[0] += f1;
            racc[1] += f2 * vx; racc[2] += f2 * vy; racc[3] += f2 * vz;
            float f3x = f3 * vx, f3y = f3 * vy, f3z = f3 * vz;
            racc[4] += f3x * vx; racc[5] += f3x * vy; racc[6] += f3x * vz;
            racc[7] += f3y * vy; racc[8] += f3y * vz; racc[9] += f3z * vz;
        }
    }
    FLUSH();
#undef FLUSH
}

// ---------------- 5. k4a: fused tn+LN + y1h = silu(Ws1 @ ln + bs1) [20 nodes/blk] ----
__global__ __launch_bounds__(256, 3) void k4a_gemm(
    const float* __restrict__ Ws1, const float* __restrict__ bs1,
    const float* __restrict__ ln_g, const float* __restrict__ ln_b) {
    __shared__ float sXT[HD * 20];
    __shared__ float sW[16 * 257];
    __shared__ float sT[20 * HD];
    __shared__ float sMu[20], sRs[20];
    const int t = threadIdx.x;
    const int nb = blockIdx.x * 20;

    for (int i = t; i < 20 * HD; i += 256) {
        int nl = i >> 7, hh = i & 127;
        const float* a = &g_acc[((size_t)(nb + nl) * HD + hh) * AS];
        float4 p0 = *(const float4*)a;
        float4 p1 = *(const float4*)(a + 4);
        float2 p2 = *(const float2*)(a + 8);
        float s1 = p0.x, wx = p0.y, wy = p0.z, wz = p0.w;
        float mxx = p1.x, mxy = p1.y, mxz = p1.z, myy = p1.w, myz = p2.x, mzz = p2.y;
        float tr3 = (mxx + myy + mzz) * (1.0f / 3.0f);
        float dxx = s1 + mxx - tr3, dyy = s1 + myy - tr3, dzz = s1 + mzz - tr3;
        float t01 = mxy - wz, t10 = mxy + wz, t02 = mxz + wy;
        float t20 = mxz - wy, t12 = myz - wx, t21 = myz + wx;
        sT[nl * HD + hh] = dxx * dxx + dyy * dyy + dzz * dzz + t01 * t01 + t10 * t10 +
                           t02 * t02 + t20 * t20 + t12 * t12 + t21 * t21;
    }
    __syncthreads();
    {
        int warp = t >> 5, lane = t & 31;
        for (int node = warp; node < 20; node += 8) {
            float s = 0.f, ss = 0.f;
#pragma unroll
            for (int j = lane; j < HD; j += 32) {
                float v = sT[node * HD + j];
                s += v; ss += v * v;
            }
#pragma unroll
            for (int o = 16; o; o >>= 1) {
                s  += __shfl_xor_sync(0xffffffffu, s, o);
                ss += __shfl_xor_sync(0xffffffffu, ss, o);
            }
            if (lane == 0) {
                float mu = s * (1.0f / HD);
                sMu[node] = mu;
                sRs[node] = rsqrtf(ss * (1.0f / HD) - mu * mu + 1e-5f);
            }
        }
    }
    __syncthreads();
    for (int i = t; i < 20 * HD; i += 256) {
        int nl = i >> 7, hh = i & 127;
        sXT[hh * 20 + nl] =
            (sT[nl * HD + hh] - sMu[nl]) * sRs[nl] * ln_g[hh] + ln_b[hh];
    }

    ull acc[10];
#pragma unroll
    for (int c = 0; c < 10; c++) acc[c] = 0ull;

    for (int h0 = 0; h0 < HD; h0 += 16) {
        __syncthreads();
#pragma unroll
        for (int r = 0; r < 16; r++) {
            int i = t + 256 * r;
            int j = i >> 4, hh = i & 15;
            sW[hh * 257 + j] = Ws1[j * HD + h0 + hh];
        }
        __syncthreads();
#pragma unroll 4
        for (int hh = 0; hh < 16; hh++) {
            float w = sW[hh * 257 + t];
            ull wp = pk2(w, w);
            const ulonglong2* xp = (const ulonglong2*)&sXT[(h0 + hh) * 20];
            ulonglong2 x0 = xp[0], x1 = xp[1];
            ulonglong2 x2 = xp[2], x3 = xp[3];
            ulonglong2 x4 = xp[4];
            acc[0] = fma2(wp, x0.x, acc[0]);
            acc[1] = fma2(wp, x0.y, acc[1]);
            acc[2] = fma2(wp, x1.x, acc[2]);
            acc[3] = fma2(wp, x1.y, acc[3]);
            acc[4] = fma2(wp, x2.x, acc[4]);
            acc[5] = fma2(wp, x2.y, acc[5]);
            acc[6] = fma2(wp, x3.x, acc[6]);
            acc[7] = fma2(wp, x3.y, acc[7]);
            acc[8] = fma2(wp, x4.x, acc[8]);
            acc[9] = fma2(wp, x4.y, acc[9]);
        }
    }
    float bb = bs1[t];
#pragma unroll
    for (int c = 0; c < 10; c++) {
        float a0, a1;
        unpk2(acc[c], a0, a1);
        g_y1h[(size_t)(nb + 2 * c) * 256 + t]     = __float2half(silu_f(a0 + bb));
        g_y1h[(size_t)(nb + 2 * c + 1) * 256 + t] = __float2half(silu_f(a1 + bb));
    }
}

// ---------------- 6. k4b_hmma: nrm = silu(Ws2 @ y1 + bs2) via HMMA ----------------
__global__ __launch_bounds__(256) void k4b_hmma(const float* __restrict__ bs2) {
    __shared__ __half sA[128 * SROW];
    __shared__ __half sB[128 * SROW];
    const int t = threadIdx.x;
    const int warp = t >> 5, lane = t & 31;
    const int nt0 = blockIdx.x * 128;
    const int jt0 = blockIdx.y * 128;

    const uint32_t sAb = smem_u32(sA);
    const uint32_t sBb = smem_u32(sB);

    float d[16][4];
#pragma unroll
    for (int n = 0; n < 16; n++)
#pragma unroll
        for (int c = 0; c < 4; c++) d[n][c] = 0.f;

    for (int kc = 0; kc < 4; kc++) {
        __syncthreads();
#pragma unroll
        for (int r = 0; r < 4; r++) {
            int i = t + 256 * r;
            int row = i >> 3, c8 = (i & 7) * 8;
            *(uint4*)&sA[row * SROW + c8] =
                *(const uint4*)&g_ws2h[(size_t)(jt0 + row) * 256 + kc * 64 + c8];
            int node = nt0 + row;
            uint4 v = make_uint4(0u, 0u, 0u, 0u);
            if (node < NN)
                v = *(const uint4*)&g_y1h[(size_t)node * 256 + kc * 64 + c8];
            *(uint4*)&sB[row * SROW + c8] = v;
        }
        __syncthreads();

#pragma unroll
        for (int ks = 0; ks < 4; ks++) {
            uint32_t af[4];
            uint32_t addr = sAb +
                2 * ((uint32_t)(warp * 16 + (lane & 15)) * SROW + ks * 16 + (lane >> 4) * 8);
            asm volatile("ldmatrix.sync.aligned.m8n8.x4.shared.b16 {%0,%1,%2,%3}, [%4];"
                         : "=r"(af[0]), "=r"(af[1]), "=r"(af[2]), "=r"(af[3]) : "r"(addr));
#pragma unroll
            for (int n = 0; n < 16; n++) {
                uint32_t b0, b1;
                uint32_t baddr = sBb +
                    2 * ((uint32_t)(n * 8 + (lane & 7)) * SROW + ks * 16 + ((lane >> 3) & 1) * 8);
                asm volatile("ldmatrix.sync.aligned.m8n8.x2.shared.b16 {%0,%1}, [%2];"
                             : "=r"(b0), "=r"(b1) : "r"(baddr));
                asm volatile(
                    "mma.sync.aligned.m16n8k16.row.col.f32.f16.f16.f32 "
                    "{%0,%1,%2,%3}, {%4,%5,%6,%7}, {%8,%9}, {%0,%1,%2,%3};"
                    : "+f"(d[n][0]), "+f"(d[n][1]), "+f"(d[n][2]), "+f"(d[n][3])
                    : "r"(af[0]), "r"(af[1]), "r"(af[2]), "r"(af[3]), "r"(b0), "r"(b1));
            }
        }
    }

    {
        int r0 = lane >> 2, cb = (lane & 3) * 2;
        int j0 = jt0 + warp * 16 + r0;
        float bb0 = bs2[j0], bb1 = bs2[j0 + 8];
#pragma unroll
        for (int n = 0; n < 16; n++) {
            int node0 = nt0 + n * 8 + cb;
            if (node0 < NN) {
                g_nrm[(size_t)node0 * 384 + j0]     = silu_f(d[n][0] + bb0);
                g_nrm[(size_t)node0 * 384 + j0 + 8] = silu_f(d[n][2] + bb1);
            }
            if (node0 + 1 < NN) {
                g_nrm[(size_t)(node0 + 1) * 384 + j0]     = silu_f(d[n][1] + bb0);
                g_nrm[(size_t)(node0 + 1) * 384 + j0 + 8] = silu_f(d[n][3] + bb1);
            }
        }
    }
}

// ---------------- 7. k5: Wt transforms + output (12 nodes/blk, 2g x 3nl tile) ----
#define K5NB 12
__global__ __launch_bounds__(256, 2) void k5_out(
    const float* __restrict__ Wt1, const float* __restrict__ Wt2,
    const float* __restrict__ Wt3, float* __restrict__ out) {
    extern __shared__ float sm[];
    float* sAcc = sm;                   // [12][128][12]
    float* sWt  = sm + K5NB * HD * AS;  // [8][390]
    int t  = threadIdx.x;
    int nb = blockIdx.x * K5NB;
    {
        float4* gsrc = (float4*)&g_acc[(size_t)nb * HD * AS];
        float4* dst = (float4*)sAcc;
        for (int i = t; i < K5NB * HD * 3; i += 256) {
            int node = nb + i / (HD * 3);
            if (node < NN) dst[i] = gsrc[i];
        }
        __syncthreads();
        float4 zz = make_float4(0.f, 0.f, 0.f, 0.f);
        for (int i = t; i < K5NB * HD * 3; i += 256) {
            int node = nb + i / (HD * 3);
            if (node < NN) gsrc[i] = zz;
        }
    }

    const int g0 = (t & 63) * 2;
    const int n0 = (t >> 6) * 3;

    ull acc[2][3][5];
#pragma unroll
    for (int gi = 0; gi < 2; gi++)
#pragma unroll
        for (int ni = 0; ni < 3; ni++)
#pragma unroll
            for (int c = 0; c < 5; c++) acc[gi][ni][c] = 0ull;

    for (int h0 = 0; h0 < HD; h0 += 8) {
        __syncthreads();
#pragma unroll
        for (int r = 0; r < 12; r++) {
            int i = t + 256 * r;
            int m = i >> 10;
            int rr = i & 1023;
            int gg = rr >> 3, hh = rr & 7;
            const float* W = (m == 0) ? Wt1 : ((m == 1) ? Wt2 : Wt3);
            sWt[hh * 390 + m * 128 + gg] = W[gg * HD + h0 + hh];
        }
        __syncthreads();
#pragma unroll
        for (int hh = 0; hh < 8; hh++) {
            const float* wrow = &sWt[hh * 390];
            float2 w1 = *(const float2*)&wrow[g0];
            float2 w2 = *(const float2*)&wrow[128 + g0];
            float2 w3 = *(const float2*)&wrow[256 + g0];
            ull pw12a = pk2(w1.x, w2.x), pw22a = pk2(w2.x, w2.x), pw33a = pk2(w3.x, w3.x);
            ull pw12b = pk2(w1.y, w2.y), pw22b = pk2(w2.y, w2.y), pw33b = pk2(w3.y, w3.y);
#pragma unroll
            for (int ni = 0; ni < 3; ni++) {
                const ull* ap = (const ull*)&sAcc[((n0 + ni) * HD + h0 + hh) * AS];
                ulonglong2 q0 = *(const ulonglong2*)ap;
                ulonglong2 q1 = *(const ulonglong2*)(ap + 2);
                ull q2 = ap[4];
                acc[0][ni][0] = fma2(pw12a, q0.x, acc[0][ni][0]);
                acc[0][ni][1] = fma2(pw22a, q0.y, acc[0][ni][1]);
                acc[0][ni][2] = fma2(pw33a, q1.x, acc[0][ni][2]);
                acc[0][ni][3] = fma2(pw33a, q1.y, acc[0][ni][3]);
                acc[0][ni][4] = fma2(pw33a, q2,   acc[0][ni][4]);
                acc[1][ni][0] = fma2(pw12b, q0.x, acc[1][ni][0]);
                acc[1][ni][1] = fma2(pw22b, q0.y, acc[1][ni][1]);
                acc[1][ni][2] = fma2(pw33b, q1.x, acc[1][ni][2]);
                acc[1][ni][3] = fma2(pw33b, q1.y, acc[1][ni][3]);
                acc[1][ni][4] = fma2(pw33b, q2,   acc[1][ni][4]);
            }
        }
    }

#pragma unroll
    for (int gi = 0; gi < 2; gi++)
#pragma unroll
    for (int ni = 0; ni < 3; ni++) {
        int n = nb + n0 + ni;
        if (n >= NN) continue;
        int g = g0 + gi;
        float nr0 = g_nrm[(size_t)n * 384 + g * 3 + 0];
        float nr1 = g_nrm[(size_t)n * 384 + g * 3 + 1];
        float nr2 = g_nrm[(size_t)n * 384 + g * 3 + 2];
        float s1, wx, wy, wz, mxx, mxy, mxz, myy, myz, mzz;
        unpk2(acc[gi][ni][0], s1, wx);
        unpk2(acc[gi][ni][1], wy, wz);
        unpk2(acc[gi][ni][2], mxx, mxy);
        unpk2(acc[gi][ni][3], mxz, myy);
        unpk2(acc[gi][ni][4], myz, mzz);
        float tr3 = (mxx + myy + mzz) * (1.0f / 3.0f);
        float dI = nr0 * s1;
        float* o = out + ((size_t)n * HD + g) * 9;
        o[0] = dI + nr2 * (mxx - tr3);
        o[1] = -nr1 * wz + nr2 * mxy;
        o[2] =  nr1 * wy + nr2 * mxz;
        o[3] =  nr1 * wz + nr2 * mxy;
        o[4] = dI + nr2 * (myy - tr3);
        o[5] = -nr1 * wx + nr2 * myz;
        o[6] = -nr1 * wy + nr2 * mxz;
        o[7] =  nr1 * wx + nr2 * myz;
        o[8] = dI + nr2 * (mzz - tr3);
    }
}

#define K5_SMEM ((K5NB * HD * AS + 8 * 390) * 4)

extern "C" void kernel_launch(void* const* d_in, const int* in_sizes, int n_in,
                              void* d_out, int out_size) {
    (void)in_sizes; (void)n_in; (void)out_size;
    const int*   z      = (const int*)d_in[0];
    const int*   ei     = (const int*)d_in[1];
    const float* ew     = (const float*)d_in[2];
    const float* evec   = (const float*)d_in[3];
    const float* eattr  = (const float*)d_in[4];
    const float* emb    = (const float*)d_in[5];
    const float* W_emb2 = (const float*)d_in[6];
    const float* b_emb2 = (const float*)d_in[7];
    const float* Wd1 = (const float*)d_in[8],  *bd1 = (const float*)d_in[9];
    const float* Wd2 = (const float*)d_in[10], *bd2 = (const float*)d_in[11];
    const float* Wd3 = (const float*)d_in[12], *bd3 = (const float*)d_in[13];
    const float* Wt1 = (const float*)d_in[14], *Wt2 = (const float*)d_in[15];
    const float* Wt3 = (const float*)d_in[16];
    const float* Ws1 = (const float*)d_in[17], *bs1 = (const float*)d_in[18];
    const float* Ws2 = (const float*)d_in[19], *bs2 = (const float*)d_in[20];
    const float* ln_g = (const float*)d_in[21], *ln_b = (const float*)d_in[22];
    float* out = (float*)d_out;

    cudaFuncSetAttribute(k5_out, cudaFuncAttributeMaxDynamicSharedMemorySize, K5_SMEM);

    kA_histT<<<189, 512>>>(ei, W_emb2);                                 // 1
    kB_multi<<<57, 1024>>>(emb, Ws2);                                   // 2
    kg_hmma<<<dim3(NE / 128, 3), 256>>>(eattr, Wd1, Wd2, Wd3, ei);      // 3
    ke_epi<<<NE / 64, 512>>>(ei, ew, evec, z, b_emb2, bd1, bd2, bd3);   // 4 <- PROFILED
    k4a_gemm<<<NN / 20, 256>>>(Ws1, bs1, ln_g, ln_b);                   // 5
    k4b_hmma<<<dim3(40, 3), 256>>>(bs2);                                // 6
    k5_out<<<(NN + K5NB - 1) / K5NB, 256, K5_SMEM>>>(Wt1, Wt2, Wt3, out); // 7
}